// round 3
// baseline (speedup 1.0000x reference)
#include <cuda_runtime.h>
#include <cstdint>

#define NN 65536
#define DD 512
#define HH 256
#define KK 16
#define LL 3
#define CC 64
#define CK 1024   // C*K

// ---------------- scratch (device globals; no allocations allowed) ----------------
__device__ float g_current[NN * DD];     // updated features
__device__ int   g_seg[NN];
__device__ int   g_cnt[CK];
__device__ int   g_off[CK];
__device__ int   g_cur[CK];
__device__ int   g_order[NN];
__device__ float g_means[CK * DD];
__device__ float g_h[CK * DD];
__device__ float g_ref[CK * DD];
__device__ float g_lp[CC * DD];
__device__ float g_comb[CC * LL * DD];
__device__ float g_t[CC * DD];

// ---------------- packed f32x2 helpers ----------------
__device__ __forceinline__ unsigned long long fma2(unsigned long long a,
                                                   unsigned long long b,
                                                   unsigned long long c) {
    unsigned long long d;
    asm("fma.rn.f32x2 %0, %1, %2, %3;" : "=l"(d) : "l"(a), "l"(b), "l"(c));
    return d;
}
__device__ __forceinline__ unsigned long long pack2(float v) {
    unsigned long long r;
    asm("mov.b64 %0, {%1, %1};" : "=l"(r) : "f"(v));
    return r;
}
__device__ __forceinline__ float2 unpack2(unsigned long long v) {
    float2 r;
    asm("mov.b64 {%0, %1}, %2;" : "=f"(r.x), "=f"(r.y) : "l"(v));
    return r;
}

// ---------------- kernel 1: fused hidden GEMM + logits + argmax -> seg ----------------
// BM=64 rows, BN=256 (=H) cols, BK=16. 256 threads: warp w owns rows w*8..w*8+7,
// lane l owns cols l*8..l*8+7 (4 f32x2 pairs).
__launch_bounds__(256)
__global__ void assign_kernel(const float* __restrict__ X,
                              const float* __restrict__ W1,   // [512,256]
                              const float* __restrict__ B1,   // [256]
                              const float* __restrict__ W2,   // [256,16]
                              const float* __restrict__ B2,   // [16]
                              const int*   __restrict__ labels)
{
    __shared__ float As[2][16][68];
    __shared__ float Bs[2][16][256];
    const int tid  = threadIdx.x;
    const int warp = tid >> 5, lane = tid & 31;
    const int row0 = blockIdx.x * 64;
    const int arow = tid >> 2, ak = (tid & 3) << 2;
    const int bk   = tid >> 4, bn = (tid & 15) << 4;

    const float* Aptr = X  + (size_t)(row0 + arow) * DD + ak;
    const float* Bptr = W1 + (size_t)bk * HH + bn;

    unsigned long long acc[8][4];
#pragma unroll
    for (int r = 0; r < 8; r++)
#pragma unroll
        for (int p = 0; p < 4; p++) acc[r][p] = 0ull;

    // initial tile
    {
        float4 a = *(const float4*)Aptr;
        As[0][ak + 0][arow] = a.x; As[0][ak + 1][arow] = a.y;
        As[0][ak + 2][arow] = a.z; As[0][ak + 3][arow] = a.w;
#pragma unroll
        for (int i = 0; i < 4; i++) {
            float4 bv = *(const float4*)(Bptr + i * 4);
            *(float4*)&Bs[0][bk][bn + i * 4] = bv;
        }
    }
    __syncthreads();

    int buf = 0;
    for (int k0 = 0; k0 < DD; k0 += 16) {
        const bool nxt = (k0 + 16) < DD;
        float4 pa; float4 pb[4];
        if (nxt) {
            pa = *(const float4*)(Aptr + k0 + 16);
#pragma unroll
            for (int i = 0; i < 4; i++)
                pb[i] = *(const float4*)(Bptr + (size_t)(k0 + 16) * HH + i * 4);
        }
#pragma unroll
        for (int kk = 0; kk < 16; kk++) {
            float4 aA = *(const float4*)&As[buf][kk][warp * 8];
            float4 aB = *(const float4*)&As[buf][kk][warp * 8 + 4];
            const ulonglong2* bp = (const ulonglong2*)&Bs[buf][kk][lane * 8];
            ulonglong2 b01 = bp[0], b23 = bp[1];
            float av[8] = {aA.x, aA.y, aA.z, aA.w, aB.x, aB.y, aB.z, aB.w};
#pragma unroll
            for (int r = 0; r < 8; r++) {
                unsigned long long a2 = pack2(av[r]);
                acc[r][0] = fma2(a2, b01.x, acc[r][0]);
                acc[r][1] = fma2(a2, b01.y, acc[r][1]);
                acc[r][2] = fma2(a2, b23.x, acc[r][2]);
                acc[r][3] = fma2(a2, b23.y, acc[r][3]);
            }
        }
        if (nxt) {
            int nb = buf ^ 1;
            As[nb][ak + 0][arow] = pa.x; As[nb][ak + 1][arow] = pa.y;
            As[nb][ak + 2][arow] = pa.z; As[nb][ak + 3][arow] = pa.w;
#pragma unroll
            for (int i = 0; i < 4; i++) *(float4*)&Bs[nb][bk][bn + i * 4] = pb[i];
            __syncthreads();
            buf = nb;
        }
    }

    // epilogue: bias + relu -> hidden
    float h[8][8];
    {
        float bb[8];
#pragma unroll
        for (int c = 0; c < 8; c++) bb[c] = B1[lane * 8 + c];
#pragma unroll
        for (int r = 0; r < 8; r++)
#pragma unroll
            for (int p = 0; p < 4; p++) {
                float2 v = unpack2(acc[r][p]);
                h[r][2 * p]     = fmaxf(v.x + bb[2 * p], 0.f);
                h[r][2 * p + 1] = fmaxf(v.y + bb[2 * p + 1], 0.f);
            }
    }

    // logits + argmax (first-max tie-break like jnp.argmax)
    float best[8]; int bi[8];
#pragma unroll
    for (int r = 0; r < 8; r++) { best[r] = -3.402823466e38f; bi[r] = 0; }
    const float* W2p = W2 + (size_t)(lane * 8) * KK;
    for (int j = 0; j < KK; j++) {
        float w2c[8];
#pragma unroll
        for (int c = 0; c < 8; c++) w2c[c] = W2p[c * KK + j];
        float pj[8];
#pragma unroll
        for (int r = 0; r < 8; r++) {
            float s = 0.f;
#pragma unroll
            for (int c = 0; c < 8; c++) s += h[r][c] * w2c[c];
            pj[r] = s;
        }
#pragma unroll
        for (int o = 16; o > 0; o >>= 1) {
#pragma unroll
            for (int r = 0; r < 8; r++)
                pj[r] += __shfl_xor_sync(0xffffffffu, pj[r], o);
        }
        float bj = B2[j];
#pragma unroll
        for (int r = 0; r < 8; r++) {
            float v = pj[r] + bj;
            if (v > best[r]) { best[r] = v; bi[r] = j; }
        }
    }
    if (lane < 8) {
        int row = row0 + warp * 8 + lane;
        g_seg[row] = labels[row] * KK + bi[lane];
    }
}

// ---------------- segment machinery (counting sort) ----------------
__global__ void zero_cnt_kernel() { g_cnt[threadIdx.x] = 0; }

__global__ void hist_kernel() {
    int i = blockIdx.x * blockDim.x + threadIdx.x;
    if (i < NN) atomicAdd(&g_cnt[g_seg[i]], 1);
}

__global__ void scan_kernel() {
    __shared__ int sh[CK];
    int t = threadIdx.x;
    int v = g_cnt[t];
    sh[t] = v;
    __syncthreads();
    for (int o = 1; o < CK; o <<= 1) {
        int u = (t >= o) ? sh[t - o] : 0;
        __syncthreads();
        sh[t] += u;
        __syncthreads();
    }
    g_off[t] = sh[t] - v;   // exclusive
    g_cur[t] = 0;
}

__global__ void scatter_kernel() {
    int i = blockIdx.x * blockDim.x + threadIdx.x;
    if (i < NN) {
        int s = g_seg[i];
        int p = atomicAdd(&g_cur[s], 1);
        g_order[g_off[s] + p] = i;
    }
}

// block s sums its rows and writes mean (sum / max(cnt,1))
__global__ void gather_mean_kernel(const float* __restrict__ X) {
    __shared__ int sidx[256];
    const int s = blockIdx.x, t = threadIdx.x;
    const int n = g_cnt[s], off = g_off[s];
    float ax = 0.f, ay = 0.f;
    for (int base = 0; base < n; base += 256) {
        int m = min(256, n - base);
        __syncthreads();
        if (t < m) sidx[t] = g_order[off + base + t];
        __syncthreads();
        for (int j = 0; j < m; j++) {
            float2 v = *(const float2*)&X[(size_t)sidx[j] * DD + 2 * t];
            ax += v.x; ay += v.y;
        }
    }
    float inv = 1.0f / (float)max(n, 1);
    g_means[(size_t)s * DD + 2 * t]     = ax * inv;
    g_means[(size_t)s * DD + 2 * t + 1] = ay * inv;
}

// ---------------- generic tiled SGEMM: C = A[M,K]@B[K,N] + bias ----------------
// BM=BN=64, BK=16, 256 threads, 4x4 per thread, double buffered.
__launch_bounds__(256)
__global__ void sgemm_kernel(const float* __restrict__ A, const float* __restrict__ B,
                             const float* __restrict__ bias, float* __restrict__ Cout,
                             int M, int Np, int Kp)
{
    __shared__ float As[2][16][68];
    __shared__ float Bs[2][16][64];
    const int tid = threadIdx.x;
    const int ty = tid >> 4, tx = tid & 15;
    const int row0 = blockIdx.x * 64, col0 = blockIdx.y * 64;
    const int arow = tid >> 2, ak = (tid & 3) << 2;
    const int bk = tid >> 4, bn = (tid & 15) << 2;

    const float* Aptr = A + (size_t)(row0 + arow) * Kp + ak;
    const float* Bptr = B + (size_t)bk * Np + col0 + bn;

    float acc[4][4];
#pragma unroll
    for (int i = 0; i < 4; i++)
#pragma unroll
        for (int j = 0; j < 4; j++) acc[i][j] = 0.f;

    {
        float4 a = *(const float4*)Aptr;
        As[0][ak + 0][arow] = a.x; As[0][ak + 1][arow] = a.y;
        As[0][ak + 2][arow] = a.z; As[0][ak + 3][arow] = a.w;
        *(float4*)&Bs[0][bk][bn] = *(const float4*)Bptr;
    }
    __syncthreads();

    int buf = 0;
    for (int k0 = 0; k0 < Kp; k0 += 16) {
        const bool nxt = (k0 + 16) < Kp;
        float4 pa, pb;
        if (nxt) {
            pa = *(const float4*)(Aptr + k0 + 16);
            pb = *(const float4*)(Bptr + (size_t)(k0 + 16) * Np);
        }
#pragma unroll
        for (int kk = 0; kk < 16; kk++) {
            float a4[4], b4[4];
            *(float4*)a4 = *(const float4*)&As[buf][kk][ty * 4];
            *(float4*)b4 = *(const float4*)&Bs[buf][kk][tx * 4];
#pragma unroll
            for (int i = 0; i < 4; i++)
#pragma unroll
                for (int j = 0; j < 4; j++) acc[i][j] += a4[i] * b4[j];
        }
        if (nxt) {
            int nb = buf ^ 1;
            As[nb][ak + 0][arow] = pa.x; As[nb][ak + 1][arow] = pa.y;
            As[nb][ak + 2][arow] = pa.z; As[nb][ak + 3][arow] = pa.w;
            *(float4*)&Bs[nb][bk][bn] = pb;
            __syncthreads();
            buf = nb;
        }
    }
#pragma unroll
    for (int i = 0; i < 4; i++)
#pragma unroll
        for (int j = 0; j < 4; j++) {
            int r = row0 + ty * 4 + i, c = col0 + tx * 4 + j;
            Cout[(size_t)r * Np + c] = acc[i][j] + bias[c];
        }
}

// ---------------- LayerNorm + ReLU in place on g_h (block per row) ----------------
__global__ void ln_relu_kernel(const float* __restrict__ gamma, const float* __restrict__ beta)
{
    __shared__ float sh[8];
    const int rowi = blockIdx.x;
    float* x = &g_h[(size_t)rowi * DD];
    const int t = threadIdx.x, lane = t & 31, w = t >> 5;
    float v0 = x[t], v1 = x[t + 256];

    float s = v0 + v1;
#pragma unroll
    for (int o = 16; o > 0; o >>= 1) s += __shfl_xor_sync(0xffffffffu, s, o);
    if (lane == 0) sh[w] = s;
    __syncthreads();
    if (t == 0) { float r = 0; for (int i = 0; i < 8; i++) r += sh[i]; sh[0] = r; }
    __syncthreads();
    float mean = sh[0] * (1.f / 512.f);
    __syncthreads();

    float d0 = v0 - mean, d1 = v1 - mean;
    float q = d0 * d0 + d1 * d1;
#pragma unroll
    for (int o = 16; o > 0; o >>= 1) q += __shfl_xor_sync(0xffffffffu, q, o);
    if (lane == 0) sh[w] = q;
    __syncthreads();
    if (t == 0) { float r = 0; for (int i = 0; i < 8; i++) r += sh[i]; sh[0] = r; }
    __syncthreads();
    float inv = rsqrtf(sh[0] * (1.f / 512.f) + 1e-5f);

    x[t]       = fmaxf(d0 * inv * gamma[t] + beta[t], 0.f);
    x[t + 256] = fmaxf(d1 * inv * gamma[t + 256] + beta[t + 256], 0.f);
}

// ---------------- lp = masked mean of refined over non-empty clusters ----------------
__global__ void lp_kernel(int l)
{
    const int c = blockIdx.x, d = threadIdx.x;
    float s = 0.f, ne = 0.f;
#pragma unroll
    for (int k = 0; k < KK; k++) {
        int sgi = c * KK + k;
        if (g_cnt[sgi] > 0) { s += g_ref[(size_t)sgi * DD + d]; ne += 1.f; }
    }
    float v = s / ne;
    g_lp[(size_t)c * DD + d] = v;
    g_comb[(size_t)c * (LL * DD) + l * DD + d] = v;
}

// ---------------- current = src + lp[label] ----------------
__global__ void update_kernel(const float* __restrict__ src, const int* __restrict__ labels)
{
    size_t idx = (size_t)blockIdx.x * blockDim.x + threadIdx.x;  // over N*128 float4
    int row = (int)(idx >> 7), q = (int)(idx & 127);
    float4 v = ((const float4*)src)[idx];
    int lab = __ldg(&labels[row]);
    float4 p = ((const float4*)g_lp)[(size_t)lab * 128 + q];
    v.x += p.x; v.y += p.y; v.z += p.z; v.w += p.w;
    ((float4*)g_current)[idx] = v;
}

// ---------------- small-M GEMM for the combiner: out[c, :512] ----------------
__global__ void smallm_kernel(const float* __restrict__ A, const float* __restrict__ B,
                              const float* __restrict__ bias, float* __restrict__ out,
                              int Kp, int relu)
{
    __shared__ float a_s[LL * DD];  // up to 1536
    const int c = blockIdx.x, t = threadIdx.x;
    for (int i = t; i < Kp; i += 512) a_s[i] = A[(size_t)c * Kp + i];
    __syncthreads();
    float acc = 0.f;
#pragma unroll 4
    for (int k = 0; k < Kp; k++) acc += a_s[k] * B[(size_t)k * DD + t];
    acc += bias[t];
    if (relu) acc = fmaxf(acc, 0.f);
    out[(size_t)c * DD + t] = acc;
}

// ---------------- host launcher ----------------
extern "C" void kernel_launch(void* const* d_in, const int* in_sizes, int n_in,
                              void* d_out, int out_size)
{
    const float* X0      = (const float*)d_in[0];
    const int*   labels  = (const int*)  d_in[1];
    const float* ch_w1   = (const float*)d_in[2];   // [3,512,256]
    const float* ch_b1   = (const float*)d_in[3];   // [3,256]
    const float* ch_w2   = (const float*)d_in[4];   // [3,256,16]
    const float* ch_b2   = (const float*)d_in[5];   // [3,16]
    const float* ref_w1  = (const float*)d_in[6];   // [3,512,512]
    const float* ref_b1  = (const float*)d_in[7];   // [3,512]
    const float* ln_g    = (const float*)d_in[8];   // [3,512]
    const float* ln_b    = (const float*)d_in[9];   // [3,512]
    const float* ref_w2  = (const float*)d_in[10];  // [3,512,512]
    const float* ref_b2  = (const float*)d_in[11];  // [3,512]
    const float* comb_w1 = (const float*)d_in[12];  // [1536,512]
    const float* comb_b1 = (const float*)d_in[13];  // [512]
    const float* comb_w2 = (const float*)d_in[14];  // [512,512]
    const float* comb_b2 = (const float*)d_in[15];  // [512]
    float* out = (float*)d_out;

    float* curp = nullptr;
    cudaGetSymbolAddress((void**)&curp, g_current);
    float* meansp = nullptr;
    cudaGetSymbolAddress((void**)&meansp, g_means);
    float* hp = nullptr;
    cudaGetSymbolAddress((void**)&hp, g_h);
    float* refp = nullptr;
    cudaGetSymbolAddress((void**)&refp, g_ref);
    float* combp = nullptr;
    cudaGetSymbolAddress((void**)&combp, g_comb);
    float* tp = nullptr;
    cudaGetSymbolAddress((void**)&tp, g_t);

    const float* X = X0;
    for (int l = 0; l < LL; l++) {
        assign_kernel<<<NN / 64, 256>>>(X,
                                        ch_w1 + (size_t)l * DD * HH,
                                        ch_b1 + (size_t)l * HH,
                                        ch_w2 + (size_t)l * HH * KK,
                                        ch_b2 + (size_t)l * KK,
                                        labels);
        zero_cnt_kernel<<<1, CK>>>();
        hist_kernel<<<NN / 256, 256>>>();
        scan_kernel<<<1, CK>>>();
        scatter_kernel<<<NN / 256, 256>>>();
        gather_mean_kernel<<<CK, 256>>>(X);

        sgemm_kernel<<<dim3(CK / 64, DD / 64), 256>>>(
            meansp, ref_w1 + (size_t)l * DD * DD, ref_b1 + (size_t)l * DD, hp,
            CK, DD, DD);
        ln_relu_kernel<<<CK, 256>>>(ln_g + (size_t)l * DD, ln_b + (size_t)l * DD);
        sgemm_kernel<<<dim3(CK / 64, DD / 64), 256>>>(
            hp, ref_w2 + (size_t)l * DD * DD, ref_b2 + (size_t)l * DD, refp,
            CK, DD, DD);
        lp_kernel<<<CC, DD>>>(l);

        if (l < LL - 1) {
            update_kernel<<<(NN * (DD / 4)) / 256, 256>>>(X, labels);
            X = curp;
        }
    }

    smallm_kernel<<<CC, DD>>>(combp, comb_w1, comb_b1, tp, LL * DD, 1);
    smallm_kernel<<<CC, DD>>>(tp, comb_w2, comb_b2, out, DD, 0);
}

// round 4
// speedup vs baseline: 1.1136x; 1.1136x over previous
#include <cuda_runtime.h>
#include <cstdint>

#define NN 65536
#define DD 512
#define HH 256
#define KK 16
#define LL 3
#define CC 64
#define CK 1024   // C*K

// ---------------- scratch (device globals; no allocations allowed) ----------------
__device__ float g_current[NN * DD];     // updated features
__device__ int   g_seg[NN];
__device__ int   g_cnt[CK];
__device__ int   g_off[CK];
__device__ int   g_cur[CK];
__device__ int   g_order[NN];
__device__ float g_means[CK * DD];
__device__ float g_h[CK * DD];
__device__ float g_ref[CK * DD];
__device__ float g_lp[CC * DD];
__device__ float g_comb[CC * LL * DD];
__device__ float g_t[CC * DD];

// ---------------- packed f32x2 helpers ----------------
__device__ __forceinline__ unsigned long long fma2(unsigned long long a,
                                                   unsigned long long b,
                                                   unsigned long long c) {
    unsigned long long d;
    asm("fma.rn.f32x2 %0, %1, %2, %3;" : "=l"(d) : "l"(a), "l"(b), "l"(c));
    return d;
}
__device__ __forceinline__ unsigned long long pack2(float v) {
    unsigned long long r;
    asm("mov.b64 %0, {%1, %1};" : "=l"(r) : "f"(v));
    return r;
}
__device__ __forceinline__ float2 unpack2(unsigned long long v) {
    float2 r;
    asm("mov.b64 {%0, %1}, %2;" : "=f"(r.x), "=f"(r.y) : "l"(v));
    return r;
}

// ---------------- cp.async helpers ----------------
__device__ __forceinline__ unsigned smem_u32(const void* p) {
    return (unsigned)__cvta_generic_to_shared(p);
}
__device__ __forceinline__ void cp16(unsigned dst, const void* src) {
    asm volatile("cp.async.cg.shared.global [%0], [%1], 16;\n" :: "r"(dst), "l"(src));
}
__device__ __forceinline__ void cp_commit() {
    asm volatile("cp.async.commit_group;\n");
}
__device__ __forceinline__ void cp_wait1() {
    asm volatile("cp.async.wait_group 1;\n");
}

// ---------------- kernel 1: fused hidden GEMM + logits + argmax -> seg ----------------
// BM=64 rows, BN=256 (=H) cols, BK=16, 3-stage cp.async pipeline.
// 256 threads: warp w owns rows w*8..w*8+7, lane l owns cols l*8..l*8+7.
#define ST 3
__launch_bounds__(256, 2)
__global__ void assign_kernel(const float* __restrict__ X,
                              const float* __restrict__ W1,   // [512,256]
                              const float* __restrict__ B1,   // [256]
                              const float* __restrict__ W2,   // [256,16]
                              const float* __restrict__ B2,   // [16]
                              const int*   __restrict__ labels)
{
    __shared__ float As[ST][64][16];    // row-major: A frag read is warp-broadcast
    __shared__ float Bs[ST][16][256];
    const int tid  = threadIdx.x;
    const int warp = tid >> 5, lane = tid & 31;
    const int row0 = blockIdx.x * 64;

    // cp.async source/dest coordinates
    const int arow = tid >> 2, ac4 = (tid & 3) << 2;                 // A: 64x16 = 256 x 16B
    const float* Asrc = X + (size_t)(row0 + arow) * DD + ac4;
    // B: 16x256 floats = 1024 x 16B chunks, 4 per thread
    const float* Bbase = W1;

    unsigned long long acc[8][4];
#pragma unroll
    for (int r = 0; r < 8; r++)
#pragma unroll
        for (int p = 0; p < 4; p++) acc[r][p] = 0ull;

    // prologue: issue stages 0 and 1
#pragma unroll
    for (int s = 0; s < 2; s++) {
        const int k0 = s * 16;
        cp16(smem_u32(&As[s][arow][ac4]), Asrc + k0);
#pragma unroll
        for (int i = 0; i < 4; i++) {
            int id = tid + i * 256;
            int br = id >> 6, bc = (id & 63) << 2;
            cp16(smem_u32(&Bs[s][br][bc]), Bbase + (size_t)(k0 + br) * HH + bc);
        }
        cp_commit();
    }

    const int NIT = DD / 16;   // 32
    int s = 0;
    for (int it = 0; it < NIT; it++) {
        cp_wait1();
        __syncthreads();

        // issue stage it+2 (writes stage (it+2)%ST == (it-1)%ST, already past sync)
        if (it + 2 < NIT) {
            const int sn = (it + 2) % ST;
            const int k0 = (it + 2) * 16;
            cp16(smem_u32(&As[sn][arow][ac4]), Asrc + k0);
#pragma unroll
            for (int i = 0; i < 4; i++) {
                int id = tid + i * 256;
                int br = id >> 6, bc = (id & 63) << 2;
                cp16(smem_u32(&Bs[sn][br][bc]), Bbase + (size_t)(k0 + br) * HH + bc);
            }
        }
        cp_commit();   // unconditional so wait_group 1 always covers current stage

        // compute on stage s
#pragma unroll
        for (int kq = 0; kq < 4; kq++) {          // 4 k-steps of 4
            float4 a4[8];
#pragma unroll
            for (int r = 0; r < 8; r++)           // broadcast LDS.128
                a4[r] = *(const float4*)&As[s][warp * 8 + r][kq * 4];
#pragma unroll
            for (int ki = 0; ki < 4; ki++) {
                const int kk = kq * 4 + ki;
                const ulonglong2* bp = (const ulonglong2*)&Bs[s][kk][lane * 8];
                ulonglong2 b01 = bp[0], b23 = bp[1];
#pragma unroll
                for (int r = 0; r < 8; r++) {
                    float av = (ki == 0) ? a4[r].x : (ki == 1) ? a4[r].y
                             : (ki == 2) ? a4[r].z : a4[r].w;
                    unsigned long long a2 = pack2(av);
                    acc[r][0] = fma2(a2, b01.x, acc[r][0]);
                    acc[r][1] = fma2(a2, b01.y, acc[r][1]);
                    acc[r][2] = fma2(a2, b23.x, acc[r][2]);
                    acc[r][3] = fma2(a2, b23.y, acc[r][3]);
                }
            }
        }
        s = (s + 1) % ST;
    }

    // epilogue: bias + relu -> hidden
    float h[8][8];
    {
        float bb[8];
#pragma unroll
        for (int c = 0; c < 8; c++) bb[c] = B1[lane * 8 + c];
#pragma unroll
        for (int r = 0; r < 8; r++)
#pragma unroll
            for (int p = 0; p < 4; p++) {
                float2 v = unpack2(acc[r][p]);
                h[r][2 * p]     = fmaxf(v.x + bb[2 * p], 0.f);
                h[r][2 * p + 1] = fmaxf(v.y + bb[2 * p + 1], 0.f);
            }
    }

    // logits + argmax (first-max tie-break like jnp.argmax)
    float best[8]; int bi[8];
#pragma unroll
    for (int r = 0; r < 8; r++) { best[r] = -3.402823466e38f; bi[r] = 0; }
    const float* W2p = W2 + (size_t)(lane * 8) * KK;
    for (int j = 0; j < KK; j++) {
        float w2c[8];
#pragma unroll
        for (int c = 0; c < 8; c++) w2c[c] = W2p[c * KK + j];
        float pj[8];
#pragma unroll
        for (int r = 0; r < 8; r++) {
            float sv = 0.f;
#pragma unroll
            for (int c = 0; c < 8; c++) sv += h[r][c] * w2c[c];
            pj[r] = sv;
        }
#pragma unroll
        for (int o = 16; o > 0; o >>= 1) {
#pragma unroll
            for (int r = 0; r < 8; r++)
                pj[r] += __shfl_xor_sync(0xffffffffu, pj[r], o);
        }
        float bj = B2[j];
#pragma unroll
        for (int r = 0; r < 8; r++) {
            float v = pj[r] + bj;
            if (v > best[r]) { best[r] = v; bi[r] = j; }
        }
    }
    if (lane < 8) {
        int row = row0 + warp * 8 + lane;
        g_seg[row] = labels[row] * KK + bi[lane];
    }
}

// ---------------- segment machinery (counting sort) ----------------
__global__ void zero_cnt_kernel() { g_cnt[threadIdx.x] = 0; }

__global__ void hist_kernel() {
    int i = blockIdx.x * blockDim.x + threadIdx.x;
    if (i < NN) atomicAdd(&g_cnt[g_seg[i]], 1);
}

__global__ void scan_kernel() {
    __shared__ int sh[CK];
    int t = threadIdx.x;
    int v = g_cnt[t];
    sh[t] = v;
    __syncthreads();
    for (int o = 1; o < CK; o <<= 1) {
        int u = (t >= o) ? sh[t - o] : 0;
        __syncthreads();
        sh[t] += u;
        __syncthreads();
    }
    g_off[t] = sh[t] - v;   // exclusive
    g_cur[t] = 0;
}

__global__ void scatter_kernel() {
    int i = blockIdx.x * blockDim.x + threadIdx.x;
    if (i < NN) {
        int sg = g_seg[i];
        int p = atomicAdd(&g_cur[sg], 1);
        g_order[g_off[sg] + p] = i;
    }
}

// block s sums its rows and writes mean (sum / max(cnt,1))
__global__ void gather_mean_kernel(const float* __restrict__ X) {
    __shared__ int sidx[256];
    const int sg = blockIdx.x, t = threadIdx.x;
    const int n = g_cnt[sg], off = g_off[sg];
    float ax = 0.f, ay = 0.f;
    for (int base = 0; base < n; base += 256) {
        int m = min(256, n - base);
        __syncthreads();
        if (t < m) sidx[t] = g_order[off + base + t];
        __syncthreads();
        for (int j = 0; j < m; j++) {
            float2 v = *(const float2*)&X[(size_t)sidx[j] * DD + 2 * t];
            ax += v.x; ay += v.y;
        }
    }
    float inv = 1.0f / (float)max(n, 1);
    g_means[(size_t)sg * DD + 2 * t]     = ax * inv;
    g_means[(size_t)sg * DD + 2 * t + 1] = ay * inv;
}

// ---------------- generic tiled SGEMM: C = A[M,K]@B[K,N] + bias ----------------
__launch_bounds__(256)
__global__ void sgemm_kernel(const float* __restrict__ A, const float* __restrict__ B,
                             const float* __restrict__ bias, float* __restrict__ Cout,
                             int M, int Np, int Kp)
{
    __shared__ float As[2][16][68];
    __shared__ float Bs[2][16][64];
    const int tid = threadIdx.x;
    const int ty = tid >> 4, tx = tid & 15;
    const int row0 = blockIdx.x * 64, col0 = blockIdx.y * 64;
    const int arow = tid >> 2, ak = (tid & 3) << 2;
    const int bk = tid >> 4, bn = (tid & 15) << 2;

    const float* Aptr = A + (size_t)(row0 + arow) * Kp + ak;
    const float* Bptr = B + (size_t)bk * Np + col0 + bn;

    float acc[4][4];
#pragma unroll
    for (int i = 0; i < 4; i++)
#pragma unroll
        for (int j = 0; j < 4; j++) acc[i][j] = 0.f;

    {
        float4 a = *(const float4*)Aptr;
        As[0][ak + 0][arow] = a.x; As[0][ak + 1][arow] = a.y;
        As[0][ak + 2][arow] = a.z; As[0][ak + 3][arow] = a.w;
        *(float4*)&Bs[0][bk][bn] = *(const float4*)Bptr;
    }
    __syncthreads();

    int buf = 0;
    for (int k0 = 0; k0 < Kp; k0 += 16) {
        const bool nxt = (k0 + 16) < Kp;
        float4 pa, pb;
        if (nxt) {
            pa = *(const float4*)(Aptr + k0 + 16);
            pb = *(const float4*)(Bptr + (size_t)(k0 + 16) * Np);
        }
#pragma unroll
        for (int kk = 0; kk < 16; kk++) {
            float a4[4], b4[4];
            *(float4*)a4 = *(const float4*)&As[buf][kk][ty * 4];
            *(float4*)b4 = *(const float4*)&Bs[buf][kk][tx * 4];
#pragma unroll
            for (int i = 0; i < 4; i++)
#pragma unroll
                for (int j = 0; j < 4; j++) acc[i][j] += a4[i] * b4[j];
        }
        if (nxt) {
            int nb = buf ^ 1;
            As[nb][ak + 0][arow] = pa.x; As[nb][ak + 1][arow] = pa.y;
            As[nb][ak + 2][arow] = pa.z; As[nb][ak + 3][arow] = pa.w;
            *(float4*)&Bs[nb][bk][bn] = pb;
            __syncthreads();
            buf = nb;
        }
    }
#pragma unroll
    for (int i = 0; i < 4; i++)
#pragma unroll
        for (int j = 0; j < 4; j++) {
            int r = row0 + ty * 4 + i, c = col0 + tx * 4 + j;
            Cout[(size_t)r * Np + c] = acc[i][j] + bias[c];
        }
}

// ---------------- LayerNorm + ReLU in place on g_h (block per row) ----------------
__global__ void ln_relu_kernel(const float* __restrict__ gamma, const float* __restrict__ beta)
{
    __shared__ float sh[8];
    const int rowi = blockIdx.x;
    float* x = &g_h[(size_t)rowi * DD];
    const int t = threadIdx.x, lane = t & 31, w = t >> 5;
    float v0 = x[t], v1 = x[t + 256];

    float s = v0 + v1;
#pragma unroll
    for (int o = 16; o > 0; o >>= 1) s += __shfl_xor_sync(0xffffffffu, s, o);
    if (lane == 0) sh[w] = s;
    __syncthreads();
    if (t == 0) { float r = 0; for (int i = 0; i < 8; i++) r += sh[i]; sh[0] = r; }
    __syncthreads();
    float mean = sh[0] * (1.f / 512.f);
    __syncthreads();

    float d0 = v0 - mean, d1 = v1 - mean;
    float q = d0 * d0 + d1 * d1;
#pragma unroll
    for (int o = 16; o > 0; o >>= 1) q += __shfl_xor_sync(0xffffffffu, q, o);
    if (lane == 0) sh[w] = q;
    __syncthreads();
    if (t == 0) { float r = 0; for (int i = 0; i < 8; i++) r += sh[i]; sh[0] = r; }
    __syncthreads();
    float inv = rsqrtf(sh[0] * (1.f / 512.f) + 1e-5f);

    x[t]       = fmaxf(d0 * inv * gamma[t] + beta[t], 0.f);
    x[t + 256] = fmaxf(d1 * inv * gamma[t + 256] + beta[t + 256], 0.f);
}

// ---------------- lp = masked mean of refined over non-empty clusters ----------------
__global__ void lp_kernel(int l)
{
    const int c = blockIdx.x, d = threadIdx.x;
    float s = 0.f, ne = 0.f;
#pragma unroll
    for (int k = 0; k < KK; k++) {
        int sgi = c * KK + k;
        if (g_cnt[sgi] > 0) { s += g_ref[(size_t)sgi * DD + d]; ne += 1.f; }
    }
    float v = s / ne;
    g_lp[(size_t)c * DD + d] = v;
    g_comb[(size_t)c * (LL * DD) + l * DD + d] = v;
}

// ---------------- current = src + lp[label] ----------------
__global__ void update_kernel(const float* __restrict__ src, const int* __restrict__ labels)
{
    size_t idx = (size_t)blockIdx.x * blockDim.x + threadIdx.x;  // over N*128 float4
    int row = (int)(idx >> 7), q = (int)(idx & 127);
    float4 v = ((const float4*)src)[idx];
    int lab = __ldg(&labels[row]);
    float4 p = ((const float4*)g_lp)[(size_t)lab * 128 + q];
    v.x += p.x; v.y += p.y; v.z += p.z; v.w += p.w;
    ((float4*)g_current)[idx] = v;
}

// ---------------- small-M GEMM for the combiner: out[c, :512] ----------------
__global__ void smallm_kernel(const float* __restrict__ A, const float* __restrict__ B,
                              const float* __restrict__ bias, float* __restrict__ out,
                              int Kp, int relu)
{
    __shared__ float a_s[LL * DD];  // up to 1536
    const int c = blockIdx.x, t = threadIdx.x;
    for (int i = t; i < Kp; i += 512) a_s[i] = A[(size_t)c * Kp + i];
    __syncthreads();
    float acc = 0.f;
#pragma unroll 4
    for (int k = 0; k < Kp; k++) acc += a_s[k] * B[(size_t)k * DD + t];
    acc += bias[t];
    if (relu) acc = fmaxf(acc, 0.f);
    out[(size_t)c * DD + t] = acc;
}

// ---------------- host launcher ----------------
extern "C" void kernel_launch(void* const* d_in, const int* in_sizes, int n_in,
                              void* d_out, int out_size)
{
    const float* X0      = (const float*)d_in[0];
    const int*   labels  = (const int*)  d_in[1];
    const float* ch_w1   = (const float*)d_in[2];   // [3,512,256]
    const float* ch_b1   = (const float*)d_in[3];   // [3,256]
    const float* ch_w2   = (const float*)d_in[4];   // [3,256,16]
    const float* ch_b2   = (const float*)d_in[5];   // [3,16]
    const float* ref_w1  = (const float*)d_in[6];   // [3,512,512]
    const float* ref_b1  = (const float*)d_in[7];   // [3,512]
    const float* ln_g    = (const float*)d_in[8];   // [3,512]
    const float* ln_b    = (const float*)d_in[9];   // [3,512]
    const float* ref_w2  = (const float*)d_in[10];  // [3,512,512]
    const float* ref_b2  = (const float*)d_in[11];  // [3,512]
    const float* comb_w1 = (const float*)d_in[12];  // [1536,512]
    const float* comb_b1 = (const float*)d_in[13];  // [512]
    const float* comb_w2 = (const float*)d_in[14];  // [512,512]
    const float* comb_b2 = (const float*)d_in[15];  // [512]
    float* out = (float*)d_out;

    float* curp = nullptr;
    cudaGetSymbolAddress((void**)&curp, g_current);
    float* meansp = nullptr;
    cudaGetSymbolAddress((void**)&meansp, g_means);
    float* hp = nullptr;
    cudaGetSymbolAddress((void**)&hp, g_h);
    float* refp = nullptr;
    cudaGetSymbolAddress((void**)&refp, g_ref);
    float* combp = nullptr;
    cudaGetSymbolAddress((void**)&combp, g_comb);
    float* tp = nullptr;
    cudaGetSymbolAddress((void**)&tp, g_t);

    const float* X = X0;
    for (int l = 0; l < LL; l++) {
        assign_kernel<<<NN / 64, 256>>>(X,
                                        ch_w1 + (size_t)l * DD * HH,
                                        ch_b1 + (size_t)l * HH,
                                        ch_w2 + (size_t)l * HH * KK,
                                        ch_b2 + (size_t)l * KK,
                                        labels);
        zero_cnt_kernel<<<1, CK>>>();
        hist_kernel<<<NN / 256, 256>>>();
        scan_kernel<<<1, CK>>>();
        scatter_kernel<<<NN / 256, 256>>>();
        gather_mean_kernel<<<CK, 256>>>(X);

        sgemm_kernel<<<dim3(CK / 64, DD / 64), 256>>>(
            meansp, ref_w1 + (size_t)l * DD * DD, ref_b1 + (size_t)l * DD, hp,
            CK, DD, DD);
        ln_relu_kernel<<<CK, 256>>>(ln_g + (size_t)l * DD, ln_b + (size_t)l * DD);
        sgemm_kernel<<<dim3(CK / 64, DD / 64), 256>>>(
            hp, ref_w2 + (size_t)l * DD * DD, ref_b2 + (size_t)l * DD, refp,
            CK, DD, DD);
        lp_kernel<<<CC, DD>>>(l);

        if (l < LL - 1) {
            update_kernel<<<(NN * (DD / 4)) / 256, 256>>>(X, labels);
            X = curp;
        }
    }

    smallm_kernel<<<CC, DD>>>(combp, comb_w1, comb_b1, tp, LL * DD, 1);
    smallm_kernel<<<CC, DD>>>(tp, comb_w2, comb_b2, out, DD, 0);
}